// round 15
// baseline (speedup 1.0000x reference)
#include <cuda_runtime.h>

#define NPTS   8192
#define BATCH  4
#define M      2048
#define KNN    32
#define CF     32
#define R2     0.04f

typedef unsigned long long ull;

// scratch (no allocations allowed)
__device__ int   g_idx[BATCH * M * KNN];
#define WTOT (35*64 + 64*64 + 64*128 + 64 + 64 + 128)   // 14784
__device__ float g_w[WTOT];
// layer-3 weights (transposed) + bias3 in constant memory (warp-uniform LDCU)
__constant__ float c_w3[64 * 128 + 128];
// per-point layer-1 pre-activation: prept[p] = W1c*p + W1f*f(p) + b1
__device__ __align__(16) ull g_pp[(size_t)BATCH * NPTS * 32];
// spatially sorted points (Morton-cell order) + original indices
__device__ float g_sx[BATCH * NPTS], g_sy[BATCH * NPTS], g_sz[BATCH * NPTS];
__device__ int   g_si[BATCH * NPTS];

// ---- packed f32x2 helpers (bit-identical IEEE f32 per lane) ----------------
__device__ __forceinline__ ull f2pack(float a, float b) {
    ull r; asm("mov.b64 %0, {%1,%2};" : "=l"(r) : "f"(a), "f"(b)); return r;
}
__device__ __forceinline__ void f2unpack(ull v, float& a, float& b) {
    asm("mov.b64 {%0,%1}, %2;" : "=f"(a), "=f"(b) : "l"(v));
}
#define F2ADD(d, a, b)    asm("add.rn.f32x2 %0, %1, %2;"     : "=l"(d) : "l"(a), "l"(b))
#define F2MUL(d, a, b)    asm("mul.rn.f32x2 %0, %1, %2;"     : "=l"(d) : "l"(a), "l"(b))
#define F2FMA(d, a, b, c) asm("fma.rn.f32x2 %0, %1, %2, %3;" : "=l"(d) : "l"(a), "l"(b), "l"(c))

__device__ __forceinline__ unsigned redux_max_u32(unsigned v) {
    unsigned r; asm("redux.sync.max.u32 %0, %1, 0xffffffff;" : "=r"(r) : "r"(v)); return r;
}
__device__ __forceinline__ unsigned redux_min_u32(unsigned v) {
    unsigned r; asm("redux.sync.min.u32 %0, %1, 0xffffffff;" : "=r"(r) : "r"(v)); return r;
}

__device__ __forceinline__ unsigned spread3_4(unsigned v) {  // 4 bits -> every 3rd
    unsigned r = (v & 1u);
    r |= (v & 2u) << 2;
    r |= (v & 4u) << 4;
    r |= (v & 8u) << 6;
    return r;
}

// ---------------------------------------------------------------------------
// Kernel 0: spatial bucket sort (blocks 0..BATCH-1) + weight-transpose prep
// (blocks BATCH..).
// ---------------------------------------------------------------------------
__global__ __launch_bounds__(1024, 1) void sort_kernel(
    const float* __restrict__ coords,
    const float* __restrict__ W1, const float* __restrict__ B1,
    const float* __restrict__ W2, const float* __restrict__ B2,
    const float* __restrict__ W3, const float* __restrict__ B3)
{
    __shared__ int cnt[4096];
    __shared__ int ss[1024];
    const int tid = threadIdx.x;

    if (blockIdx.x >= BATCH) {               // prep portion
        int i = (blockIdx.x - BATCH) * 1024 + tid;
        if (i < WTOT) {
            float v;
            if (i < 2240)       { int j = i;         int c = j >> 6, o = j & 63;  v = W1[o * 35 + c]; }
            else if (i < 6336)  { int j = i - 2240;  int c = j >> 6, o = j & 63;  v = W2[o * 64 + c]; }
            else if (i < 14528) { int j = i - 6336;  int c = j >> 7, o = j & 127; v = W3[o * 64 + c]; }
            else if (i < 14592) v = B1[i - 14528];
            else if (i < 14656) v = B2[i - 14592];
            else                v = B3[i - 14656];
            g_w[i] = v;
        }
        return;
    }

    const int b = blockIdx.x;
    const float* X = coords + (size_t)b * 3 * NPTS;
    const float* Y = X + NPTS;
    const float* Z = X + 2 * NPTS;

    for (int i = tid; i < 4096; i += 1024) cnt[i] = 0;
    __syncthreads();

    int cell8[8];
#pragma unroll
    for (int i = 0; i < 8; i++) {
        int n = tid + i * 1024;
        int cx = min(15, (int)(X[n] * 16.0f));
        int cy = min(15, (int)(Y[n] * 16.0f));
        int cz = min(15, (int)(Z[n] * 16.0f));
        int cell = spread3_4(cx) | (spread3_4(cy) << 1) | (spread3_4(cz) << 2);
        cell8[i] = cell;
        atomicAdd(&cnt[cell], 1);
    }
    __syncthreads();

    int l0 = cnt[4 * tid], l1 = cnt[4 * tid + 1], l2 = cnt[4 * tid + 2], l3 = cnt[4 * tid + 3];
    int local = l0 + l1 + l2 + l3;
    ss[tid] = local;
    __syncthreads();
    for (int off = 1; off < 1024; off <<= 1) {
        int v = (tid >= off) ? ss[tid - off] : 0;
        __syncthreads();
        ss[tid] += v;
        __syncthreads();
    }
    int ex = ss[tid] - local;
    cnt[4 * tid]     = ex;
    cnt[4 * tid + 1] = ex + l0;
    cnt[4 * tid + 2] = ex + l0 + l1;
    cnt[4 * tid + 3] = ex + l0 + l1 + l2;
    __syncthreads();

#pragma unroll
    for (int i = 0; i < 8; i++) {
        int n = tid + i * 1024;
        int pos = atomicAdd(&cnt[cell8[i]], 1);
        g_sx[b * NPTS + pos] = X[n];
        g_sy[b * NPTS + pos] = Y[n];
        g_sz[b * NPTS + pos] = Z[n];
        g_si[b * NPTS + pos] = n;
    }
}

// ---------------------------------------------------------------------------
// Kernel 0.5: per-point layer-1 pre-activation (no relu).
// ---------------------------------------------------------------------------
__global__ __launch_bounds__(256, 3) void prept_kernel(
    const float* __restrict__ coords, const float* __restrict__ feats)
{
    extern __shared__ float sm[];           // w1t (2240) + b1 (64)
    const int tid = threadIdx.x;
    for (int i = tid; i < 560; i += 256)
        ((float4*)sm)[i] = ((const float4*)g_w)[i];
    if (tid < 64) sm[2240 + tid] = g_w[14528 + tid];
    __syncthreads();

    const int ng = blockIdx.x * 256 + tid;   // global point id = b*NPTS + n
    const int b = ng >> 13, n = ng & (NPTS - 1);
    const float* X = coords + (size_t)b * 3 * NPTS;
    const float* F = feats + (size_t)b * CF * NPTS;

    float in[35];
    in[0] = X[n];
    in[1] = X[NPTS + n];
    in[2] = X[2 * NPTS + n];
#pragma unroll
    for (int c = 0; c < CF; c++) in[3 + c] = F[c * NPTS + n];

    const ull* bp = (const ull*)(sm + 2240);
    ull* O = g_pp + (size_t)ng * 32;

#pragma unroll
    for (int half = 0; half < 2; half++) {
        ull acc[16];
#pragma unroll
        for (int i = 0; i < 16; i++) acc[i] = bp[half * 16 + i];
#pragma unroll
        for (int c = 0; c < 35; c++) {
            const ull xx = f2pack(in[c], in[c]);
            const ulonglong2* pw = (const ulonglong2*)(sm + c * 64 + half * 32);
#pragma unroll
            for (int i = 0; i < 8; i++) {
                const ulonglong2 w = pw[i];
                F2FMA(acc[2 * i],     w.x, xx, acc[2 * i]);
                F2FMA(acc[2 * i + 1], w.y, xx, acc[2 * i + 1]);
            }
        }
#pragma unroll
        for (int i2 = 0; i2 < 8; i2++) {
            ulonglong2 v; v.x = acc[2 * i2]; v.y = acc[2 * i2 + 1];
            ((ulonglong2*)O)[half * 8 + i2] = v;
        }
    }
}

// ---------------------------------------------------------------------------
// Kernel 1: furthest point sampling (round-12/14 proven logic). Coords staged
// in smem as float4 so the per-iteration centroid fetch is ONE broadcast
// LDS.128 (was 3 LDS.32) on the every-warp serial tail.
// ---------------------------------------------------------------------------
__global__ __launch_bounds__(512, 1) void fps_kernel(
    const float* __restrict__ coords, float* __restrict__ centers)
{
    extern __shared__ float4 smc4[];         // [NPTS] xyz_ + skey tail
    const int b = blockIdx.x, tid = threadIdx.x;
    const int wid = tid >> 5, lane = tid & 31;
    const float* X = coords + (size_t)b * 3 * NPTS;
    const float* Y = X + NPTS;
    const float* Z = X + 2 * NPTS;
    const float* SX = g_sx + b * NPTS;
    const float* SY = g_sy + b * NPTS;
    const float* SZ = g_sz + b * NPTS;
    const int*   SI = g_si + b * NPTS;

    for (int i = tid; i < NPTS; i += 512)
        smc4[i] = make_float4(X[i], Y[i], Z[i], 0.0f);
    ull* skey = (ull*)(smc4 + NPTS);         // [2][16]

    ull px2[8], py2[8], pz2[8];
    int oi[16];
    float dl[16];
    float bxmin = 1e30f, bxmax = -1e30f, bymin = 1e30f, bymax = -1e30f,
          bzmin = 1e30f, bzmax = -1e30f;
    const int base = tid * 16;
#pragma unroll
    for (int j = 0; j < 8; j++) {
        float x0 = SX[base + 2*j], x1 = SX[base + 2*j + 1];
        float y0 = SY[base + 2*j], y1 = SY[base + 2*j + 1];
        float z0 = SZ[base + 2*j], z1 = SZ[base + 2*j + 1];
        px2[j] = f2pack(x0, x1); py2[j] = f2pack(y0, y1); pz2[j] = f2pack(z0, z1);
        oi[2*j] = SI[base + 2*j]; oi[2*j + 1] = SI[base + 2*j + 1];
        dl[2*j] = 1e30f; dl[2*j + 1] = 1e30f;
        bxmin = fminf(bxmin, fminf(x0, x1)); bxmax = fmaxf(bxmax, fmaxf(x0, x1));
        bymin = fminf(bymin, fminf(y0, y1)); bymax = fmaxf(bymax, fmaxf(y0, y1));
        bzmin = fminf(bzmin, fminf(z0, z1)); bzmax = fmaxf(bzmax, fmaxf(z0, z1));
    }

    float* ox = centers + (size_t)b * 3 * M;
    float* oy = ox + M;
    float* oz = ox + 2 * M;

    float cx = __ldg(X), cy = __ldg(Y), cz = __ldg(Z);
    if (tid == 0) { ox[0] = cx; oy[0] = cy; oz[0] = cz; }

    float bm = 1e30f;
    int   bi = 0x7fffffff;

    for (int s = 0; s < M; s++) {
        float tx = fmaxf(fmaxf(bxmin - cx, cx - bxmax), 0.0f);
        float ty = fmaxf(fmaxf(bymin - cy, cy - bymax), 0.0f);
        float tz = fmaxf(fmaxf(bzmin - cz, cz - bzmax), 0.0f);
        float lb2 = fmaf(tz, tz, fmaf(ty, ty, tx * tx));

        if (!(lb2 * 0.999f > bm)) {
            const ull ncx = f2pack(-cx, -cx);
            const ull ncy = f2pack(-cy, -cy);
            const ull ncz = f2pack(-cz, -cz);
#pragma unroll
            for (int j = 0; j < 8; j++) {
                ull dx, dy, dz, t;
                F2ADD(dx, px2[j], ncx);
                F2ADD(dy, py2[j], ncy);
                F2ADD(dz, pz2[j], ncz);
                F2MUL(t, dx, dx);
                F2FMA(t, dy, dy, t);
                F2FMA(t, dz, dz, t);
                float t0, t1; f2unpack(t, t0, t1);
                dl[2*j]     = fminf(dl[2*j],     t0);
                dl[2*j + 1] = fminf(dl[2*j + 1], t1);
            }
            float m0 = fmaxf(dl[0],  dl[1]),  m1 = fmaxf(dl[2],  dl[3]);
            float m2 = fmaxf(dl[4],  dl[5]),  m3 = fmaxf(dl[6],  dl[7]);
            float m4 = fmaxf(dl[8],  dl[9]),  m5 = fmaxf(dl[10], dl[11]);
            float m6 = fmaxf(dl[12], dl[13]), m7 = fmaxf(dl[14], dl[15]);
            m0 = fmaxf(m0, m1); m2 = fmaxf(m2, m3);
            m4 = fmaxf(m4, m5); m6 = fmaxf(m6, m7);
            m0 = fmaxf(m0, m2); m4 = fmaxf(m4, m6);
            bm = fmaxf(m0, m4);
            int mi = 0x7fffffff;
#pragma unroll
            for (int k = 0; k < 16; k++)
                if (dl[k] == bm) mi = min(mi, oi[k]);
            bi = mi;
        }

        unsigned mb = __float_as_uint(bm);
        unsigned wm = redux_max_u32(mb);
        unsigned ci = (mb == wm) ? (unsigned)bi : 0x7fffffffu;
        unsigned wi = redux_min_u32(ci);
        if (lane == 0) skey[(s & 1) * 16 + wid] = ((ull)wm << 32) | wi;
        __syncthreads();

        ull k = skey[(s & 1) * 16 + (lane & 15)];
        unsigned v  = (unsigned)(k >> 32);
        unsigned ii = (unsigned)k;
        unsigned gm = redux_max_u32(v);
        unsigned c2 = (v == gm) ? ii : 0x7fffffffu;
        unsigned gi = redux_min_u32(c2);

        const float4 c4 = smc4[gi];           // one broadcast LDS.128
        cx = c4.x; cy = c4.y; cz = c4.z;
        if (tid == 0 && s + 1 < M) {
            ox[s + 1] = cx; oy[s + 1] = cy; oz[s + 1] = cz;
        }
    }
}

// ---------------------------------------------------------------------------
// Kernel 2: ball query (proven config, untouched).
// ---------------------------------------------------------------------------
__global__ __launch_bounds__(128) void bq_kernel(
    const float* __restrict__ coords, const float* __restrict__ centers)
{
    const int gw   = (blockIdx.x * blockDim.x + threadIdx.x) >> 5;
    const int lane = threadIdx.x & 31;
    if (gw >= BATCH * M) return;
    const int b = gw >> 11, m = gw & (M - 1);

    const float* X = coords + (size_t)b * 3 * NPTS;
    const float* Y = X + NPTS;
    const float* Z = X + 2 * NPTS;
    const float* C = centers + (size_t)b * 3 * M;
    const float cx = C[m], cy = C[M + m], cz = C[2 * M + m];

    const int base = gw * KNN;
    int cnt = 0, firstn = 0;

    for (int c0 = 0; c0 < NPTS && cnt < KNN; c0 += 128) {
        unsigned msk[4];
#pragma unroll
        for (int u = 0; u < 4; u++) {
            const int n = c0 + u * 32 + lane;
            float dx = X[n] - cx, dy = Y[n] - cy, dz = Z[n] - cz;
            float d2 = fmaf(dz, dz, fmaf(dy, dy, dx * dx));
            msk[u] = __ballot_sync(0xffffffffu, d2 < R2);
        }
#pragma unroll
        for (int u = 0; u < 4; u++) {
            if (cnt < KNN) {
                const unsigned mask = msk[u];
                const int n = c0 + u * 32 + lane;
                if (cnt == 0 && mask) firstn = c0 + u * 32 + __ffs(mask) - 1;
                bool hit = (mask >> lane) & 1u;
                int pos = cnt + __popc(mask & ((1u << lane) - 1u));
                if (hit && pos < KNN) g_idx[base + pos] = n;
                cnt += __popc(mask);
            }
        }
    }
    for (int j = cnt + lane; j < KNN; j += 32) g_idx[base + j] = firstn;
}

// ---------------------------------------------------------------------------
// Kernel 3: MLP consumer. Layer-3 weights read from __constant__ (uniform
// address -> LDCU, floor 1/cyc) instead of smem (LDS floor ~4 at nw>=4);
// this removes ~2/3 of the per-thread shared-load issue traffic.
// ---------------------------------------------------------------------------
__global__ __launch_bounds__(256, 2) void mlp2_kernel(
    const float* __restrict__ centers, float* __restrict__ out)
{
    extern __shared__ float sm[];            // w2t 4096 | b2 64 | w1c 192
    const int tid = threadIdx.x;
    for (int i = tid; i < 1024; i += 256)
        ((float4*)sm)[i] = ((const float4*)(g_w + 2240))[i];       // w2t
    if (tid < 16) ((float4*)(sm + 4096))[tid] = ((const float4*)(g_w + 14592))[tid]; // b2
    if (tid < 48) ((float4*)(sm + 4160))[tid] = ((const float4*)g_w)[tid];           // w1c
    __syncthreads();

    float* w2t = sm;                 // [64][64]
    const ull* bias2 = (const ull*)(sm + 4096);
    const float* w1c = sm + 4160;    // [3][64]
    const ull* bias3c = (const ull*)(c_w3 + 8192);

    const int wid = tid >> 5, lane = tid & 31;
    const int gw = blockIdx.x * 8 + wid;
    const int b = gw >> 11, m = gw & (M - 1);

    const float* C = centers + (size_t)b * 3 * M;
    const float cx = C[m], cy = C[M + m], cz = C[2 * M + m];

    // center term: lane holds channel-pair 'lane' of (-W1c*c)
    ull pcv;
    {
        const ull w0 = ((const ull*)(w1c))[lane];
        const ull w1 = ((const ull*)(w1c + 64))[lane];
        const ull w2 = ((const ull*)(w1c + 128))[lane];
        F2MUL(pcv, w0, f2pack(-cx, -cx));
        F2FMA(pcv, w1, f2pack(-cy, -cy), pcv);
        F2FMA(pcv, w2, f2pack(-cz, -cz), pcv);
    }

    const int idx = g_idx[gw * KNN + lane];
    const ulonglong2* PP =
        (const ulonglong2*)(g_pp + ((size_t)(b * NPTS + idx)) * 32);

    ull acc[32];
#pragma unroll
    for (int i = 0; i < 32; i++) acc[i] = bias2[i];

    for (int blk = 0; blk < 4; blk++) {
        ulonglong2 pp2[4];
#pragma unroll
        for (int t2 = 0; t2 < 4; t2++) pp2[t2] = PP[blk * 4 + t2];
#pragma unroll
        for (int t = 0; t < 8; t++) {
            ull ppv = (t & 1) ? pp2[t >> 1].y : pp2[t >> 1].x;
            ull pv  = __shfl_sync(0xffffffffu, pcv, blk * 8 + t);
            ull hv; F2ADD(hv, ppv, pv);
            float x0, x1; f2unpack(hv, x0, x1);
            x0 = fmaxf(x0, 0.f); x1 = fmaxf(x1, 0.f);
            const ull xx0 = f2pack(x0, x0), xx1 = f2pack(x1, x1);
            const int c = blk * 16 + 2 * t;
            const ulonglong2* pw0 = (const ulonglong2*)(w2t + c * 64);
            const ulonglong2* pw1 = (const ulonglong2*)(w2t + (c + 1) * 64);
#pragma unroll
            for (int i = 0; i < 16; i++) {
                const ulonglong2 w = pw0[i];
                F2FMA(acc[2 * i],     w.x, xx0, acc[2 * i]);
                F2FMA(acc[2 * i + 1], w.y, xx0, acc[2 * i + 1]);
            }
#pragma unroll
            for (int i = 0; i < 16; i++) {
                const ulonglong2 w = pw1[i];
                F2FMA(acc[2 * i],     w.x, xx1, acc[2 * i]);
                F2FMA(acc[2 * i + 1], w.y, xx1, acc[2 * i + 1]);
            }
        }
    }

    float h2[64];
#pragma unroll
    for (int i = 0; i < 32; i++) {
        float a, c2; f2unpack(acc[i], a, c2);
        h2[2 * i] = fmaxf(a, 0.f); h2[2 * i + 1] = fmaxf(c2, 0.f);
    }

    float* O = out + (size_t)b * 128 * M + m;
    for (int q = 0; q < 4; q++) {
        ull a3[16];
#pragma unroll
        for (int i = 0; i < 16; i++) a3[i] = bias3c[q * 16 + i];
#pragma unroll
        for (int c = 0; c < 64; c++) {
            const ull xx = f2pack(h2[c], h2[c]);
            const ulonglong2* pw = (const ulonglong2*)(c_w3 + c * 128 + q * 32);
#pragma unroll
            for (int i = 0; i < 8; i++) {
                const ulonglong2 w = pw[i];
                F2FMA(a3[2 * i],     w.x, xx, a3[2 * i]);
                F2FMA(a3[2 * i + 1], w.y, xx, a3[2 * i + 1]);
            }
        }
#pragma unroll
        for (int i = 0; i < 16; i++) {
            float u, v; f2unpack(a3[i], u, v);
            u = fmaxf(u, 0.f); v = fmaxf(v, 0.f);
#pragma unroll
            for (int off = 16; off; off >>= 1) {
                u = fmaxf(u, __shfl_xor_sync(0xffffffffu, u, off));
                v = fmaxf(v, __shfl_xor_sync(0xffffffffu, v, off));
            }
            if (lane == 0) {
                O[(q * 32 + 2 * i) * M]     = u;
                O[(q * 32 + 2 * i + 1) * M] = v;
            }
        }
    }
}

// ---------------------------------------------------------------------------
extern "C" void kernel_launch(void* const* d_in, const int* in_sizes, int n_in,
                              void* d_out, int out_size)
{
    const float* feats  = (const float*)d_in[0];
    const float* coords = (const float*)d_in[1];
    const float* W1 = (const float*)d_in[2];
    const float* B1 = (const float*)d_in[3];
    const float* W2 = (const float*)d_in[4];
    const float* B2 = (const float*)d_in[5];
    const float* W3 = (const float*)d_in[6];
    const float* B3 = (const float*)d_in[7];

    float* out     = (float*)d_out;
    float* centers = out + (size_t)BATCH * 128 * M;

    sort_kernel<<<BATCH + (WTOT + 1023) / 1024, 1024>>>(
        coords, W1, B1, W2, B2, W3, B3);

    // copy transposed layer-3 weights + b3 into constant memory (D2D, async)
    float* g_w_dev = nullptr;
    cudaGetSymbolAddress((void**)&g_w_dev, g_w);
    cudaMemcpyToSymbolAsync(c_w3, g_w_dev + 6336, 8192 * sizeof(float), 0,
                            cudaMemcpyDeviceToDevice, 0);
    cudaMemcpyToSymbolAsync(c_w3, g_w_dev + 14656, 128 * sizeof(float),
                            8192 * sizeof(float), cudaMemcpyDeviceToDevice, 0);

    prept_kernel<<<(BATCH * NPTS) / 256, 256, 2304 * 4>>>(coords, feats);

    const int SMEMF = NPTS * 16 + 2 * 16 * 8;
    cudaFuncSetAttribute(fps_kernel, cudaFuncAttributeMaxDynamicSharedMemorySize, SMEMF);
    fps_kernel<<<BATCH, 512, SMEMF>>>(coords, centers);

    bq_kernel<<<(BATCH * M) / 4, 128>>>(coords, centers);

    const int SMEM2 = 4352 * 4;
    cudaFuncSetAttribute(mlp2_kernel, cudaFuncAttributeMaxDynamicSharedMemorySize, SMEM2);
    mlp2_kernel<<<(BATCH * M) / 8, 256, SMEM2>>>(centers, out);
}

// round 16
// speedup vs baseline: 4.3837x; 4.3837x over previous
#include <cuda_runtime.h>

#define NPTS   8192
#define BATCH  4
#define M      2048
#define KNN    32
#define CF     32
#define R2     0.04f

typedef unsigned long long ull;

// scratch (no allocations allowed)
__device__ int   g_idx[BATCH * M * KNN];
#define WTOT (35*64 + 64*64 + 64*128 + 64 + 64 + 128)   // 14784
__device__ float g_w[WTOT];
// per-point layer-1 pre-activation: prept[p] = W1c*p + W1f*f(p) + b1
__device__ __align__(16) ull g_pp[(size_t)BATCH * NPTS * 32];
// spatially sorted points (Morton-cell order) + original indices
__device__ float g_sx[BATCH * NPTS], g_sy[BATCH * NPTS], g_sz[BATCH * NPTS];
__device__ int   g_si[BATCH * NPTS];

// ---- packed f32x2 helpers (bit-identical IEEE f32 per lane) ----------------
__device__ __forceinline__ ull f2pack(float a, float b) {
    ull r; asm("mov.b64 %0, {%1,%2};" : "=l"(r) : "f"(a), "f"(b)); return r;
}
__device__ __forceinline__ void f2unpack(ull v, float& a, float& b) {
    asm("mov.b64 {%0,%1}, %2;" : "=f"(a), "=f"(b) : "l"(v));
}
#define F2ADD(d, a, b)    asm("add.rn.f32x2 %0, %1, %2;"     : "=l"(d) : "l"(a), "l"(b))
#define F2MUL(d, a, b)    asm("mul.rn.f32x2 %0, %1, %2;"     : "=l"(d) : "l"(a), "l"(b))
#define F2FMA(d, a, b, c) asm("fma.rn.f32x2 %0, %1, %2, %3;" : "=l"(d) : "l"(a), "l"(b), "l"(c))

__device__ __forceinline__ unsigned redux_max_u32(unsigned v) {
    unsigned r; asm("redux.sync.max.u32 %0, %1, 0xffffffff;" : "=r"(r) : "r"(v)); return r;
}
__device__ __forceinline__ unsigned redux_min_u32(unsigned v) {
    unsigned r; asm("redux.sync.min.u32 %0, %1, 0xffffffff;" : "=r"(r) : "r"(v)); return r;
}

__device__ __forceinline__ unsigned spread3_4(unsigned v) {  // 4 bits -> every 3rd
    unsigned r = (v & 1u);
    r |= (v & 2u) << 2;
    r |= (v & 4u) << 4;
    r |= (v & 8u) << 6;
    return r;
}

// ---------------------------------------------------------------------------
// Kernel 0: spatial bucket sort (blocks 0..BATCH-1) + weight-transpose prep
// (blocks BATCH..).
// ---------------------------------------------------------------------------
__global__ __launch_bounds__(1024, 1) void sort_kernel(
    const float* __restrict__ coords,
    const float* __restrict__ W1, const float* __restrict__ B1,
    const float* __restrict__ W2, const float* __restrict__ B2,
    const float* __restrict__ W3, const float* __restrict__ B3)
{
    __shared__ int cnt[4096];
    __shared__ int ss[1024];
    const int tid = threadIdx.x;

    if (blockIdx.x >= BATCH) {               // prep portion
        int i = (blockIdx.x - BATCH) * 1024 + tid;
        if (i < WTOT) {
            float v;
            if (i < 2240)       { int j = i;         int c = j >> 6, o = j & 63;  v = W1[o * 35 + c]; }
            else if (i < 6336)  { int j = i - 2240;  int c = j >> 6, o = j & 63;  v = W2[o * 64 + c]; }
            else if (i < 14528) { int j = i - 6336;  int c = j >> 7, o = j & 127; v = W3[o * 64 + c]; }
            else if (i < 14592) v = B1[i - 14528];
            else if (i < 14656) v = B2[i - 14592];
            else                v = B3[i - 14656];
            g_w[i] = v;
        }
        return;
    }

    const int b = blockIdx.x;
    const float* X = coords + (size_t)b * 3 * NPTS;
    const float* Y = X + NPTS;
    const float* Z = X + 2 * NPTS;

    for (int i = tid; i < 4096; i += 1024) cnt[i] = 0;
    __syncthreads();

    int cell8[8];
#pragma unroll
    for (int i = 0; i < 8; i++) {
        int n = tid + i * 1024;
        int cx = min(15, (int)(X[n] * 16.0f));
        int cy = min(15, (int)(Y[n] * 16.0f));
        int cz = min(15, (int)(Z[n] * 16.0f));
        int cell = spread3_4(cx) | (spread3_4(cy) << 1) | (spread3_4(cz) << 2);
        cell8[i] = cell;
        atomicAdd(&cnt[cell], 1);
    }
    __syncthreads();

    int l0 = cnt[4 * tid], l1 = cnt[4 * tid + 1], l2 = cnt[4 * tid + 2], l3 = cnt[4 * tid + 3];
    int local = l0 + l1 + l2 + l3;
    ss[tid] = local;
    __syncthreads();
    for (int off = 1; off < 1024; off <<= 1) {
        int v = (tid >= off) ? ss[tid - off] : 0;
        __syncthreads();
        ss[tid] += v;
        __syncthreads();
    }
    int ex = ss[tid] - local;
    cnt[4 * tid]     = ex;
    cnt[4 * tid + 1] = ex + l0;
    cnt[4 * tid + 2] = ex + l0 + l1;
    cnt[4 * tid + 3] = ex + l0 + l1 + l2;
    __syncthreads();

#pragma unroll
    for (int i = 0; i < 8; i++) {
        int n = tid + i * 1024;
        int pos = atomicAdd(&cnt[cell8[i]], 1);
        g_sx[b * NPTS + pos] = X[n];
        g_sy[b * NPTS + pos] = Y[n];
        g_sz[b * NPTS + pos] = Z[n];
        g_si[b * NPTS + pos] = n;
    }
}

// ---------------------------------------------------------------------------
// Kernel 0.5: per-point layer-1 pre-activation (no relu).
// ---------------------------------------------------------------------------
__global__ __launch_bounds__(256, 3) void prept_kernel(
    const float* __restrict__ coords, const float* __restrict__ feats)
{
    extern __shared__ float sm[];           // w1t (2240) + b1 (64)
    const int tid = threadIdx.x;
    for (int i = tid; i < 560; i += 256)
        ((float4*)sm)[i] = ((const float4*)g_w)[i];
    if (tid < 64) sm[2240 + tid] = g_w[14528 + tid];
    __syncthreads();

    const int ng = blockIdx.x * 256 + tid;   // global point id = b*NPTS + n
    const int b = ng >> 13, n = ng & (NPTS - 1);
    const float* X = coords + (size_t)b * 3 * NPTS;
    const float* F = feats + (size_t)b * CF * NPTS;

    float in[35];
    in[0] = X[n];
    in[1] = X[NPTS + n];
    in[2] = X[2 * NPTS + n];
#pragma unroll
    for (int c = 0; c < CF; c++) in[3 + c] = F[c * NPTS + n];

    const ull* bp = (const ull*)(sm + 2240);
    ull* O = g_pp + (size_t)ng * 32;

#pragma unroll
    for (int half = 0; half < 2; half++) {
        ull acc[16];
#pragma unroll
        for (int i = 0; i < 16; i++) acc[i] = bp[half * 16 + i];
#pragma unroll
        for (int c = 0; c < 35; c++) {
            const ull xx = f2pack(in[c], in[c]);
            const ulonglong2* pw = (const ulonglong2*)(sm + c * 64 + half * 32);
#pragma unroll
            for (int i = 0; i < 8; i++) {
                const ulonglong2 w = pw[i];
                F2FMA(acc[2 * i],     w.x, xx, acc[2 * i]);
                F2FMA(acc[2 * i + 1], w.y, xx, acc[2 * i + 1]);
            }
        }
#pragma unroll
        for (int i2 = 0; i2 < 8; i2++) {
            ulonglong2 v; v.x = acc[2 * i2]; v.y = acc[2 * i2 + 1];
            ((ulonglong2*)O)[half * 8 + i2] = v;
        }
    }
}

// ---------------------------------------------------------------------------
// Kernel 1: furthest point sampling (proven logic). Coords staged in smem as
// float4 so the per-iteration centroid fetch is ONE broadcast LDS.128.
// ---------------------------------------------------------------------------
__global__ __launch_bounds__(512, 1) void fps_kernel(
    const float* __restrict__ coords, float* __restrict__ centers)
{
    extern __shared__ float4 smc4[];         // [NPTS] xyz_ + skey tail
    const int b = blockIdx.x, tid = threadIdx.x;
    const int wid = tid >> 5, lane = tid & 31;
    const float* X = coords + (size_t)b * 3 * NPTS;
    const float* Y = X + NPTS;
    const float* Z = X + 2 * NPTS;
    const float* SX = g_sx + b * NPTS;
    const float* SY = g_sy + b * NPTS;
    const float* SZ = g_sz + b * NPTS;
    const int*   SI = g_si + b * NPTS;

    for (int i = tid; i < NPTS; i += 512)
        smc4[i] = make_float4(X[i], Y[i], Z[i], 0.0f);
    ull* skey = (ull*)(smc4 + NPTS);         // [2][16]

    ull px2[8], py2[8], pz2[8];
    int oi[16];
    float dl[16];
    float bxmin = 1e30f, bxmax = -1e30f, bymin = 1e30f, bymax = -1e30f,
          bzmin = 1e30f, bzmax = -1e30f;
    const int base = tid * 16;
#pragma unroll
    for (int j = 0; j < 8; j++) {
        float x0 = SX[base + 2*j], x1 = SX[base + 2*j + 1];
        float y0 = SY[base + 2*j], y1 = SY[base + 2*j + 1];
        float z0 = SZ[base + 2*j], z1 = SZ[base + 2*j + 1];
        px2[j] = f2pack(x0, x1); py2[j] = f2pack(y0, y1); pz2[j] = f2pack(z0, z1);
        oi[2*j] = SI[base + 2*j]; oi[2*j + 1] = SI[base + 2*j + 1];
        dl[2*j] = 1e30f; dl[2*j + 1] = 1e30f;
        bxmin = fminf(bxmin, fminf(x0, x1)); bxmax = fmaxf(bxmax, fmaxf(x0, x1));
        bymin = fminf(bymin, fminf(y0, y1)); bymax = fmaxf(bymax, fmaxf(y0, y1));
        bzmin = fminf(bzmin, fminf(z0, z1)); bzmax = fmaxf(bzmax, fmaxf(z0, z1));
    }

    float* ox = centers + (size_t)b * 3 * M;
    float* oy = ox + M;
    float* oz = ox + 2 * M;

    float cx = __ldg(X), cy = __ldg(Y), cz = __ldg(Z);
    if (tid == 0) { ox[0] = cx; oy[0] = cy; oz[0] = cz; }

    float bm = 1e30f;
    int   bi = 0x7fffffff;

    for (int s = 0; s < M; s++) {
        float tx = fmaxf(fmaxf(bxmin - cx, cx - bxmax), 0.0f);
        float ty = fmaxf(fmaxf(bymin - cy, cy - bymax), 0.0f);
        float tz = fmaxf(fmaxf(bzmin - cz, cz - bzmax), 0.0f);
        float lb2 = fmaf(tz, tz, fmaf(ty, ty, tx * tx));

        if (!(lb2 * 0.999f > bm)) {
            const ull ncx = f2pack(-cx, -cx);
            const ull ncy = f2pack(-cy, -cy);
            const ull ncz = f2pack(-cz, -cz);
#pragma unroll
            for (int j = 0; j < 8; j++) {
                ull dx, dy, dz, t;
                F2ADD(dx, px2[j], ncx);
                F2ADD(dy, py2[j], ncy);
                F2ADD(dz, pz2[j], ncz);
                F2MUL(t, dx, dx);
                F2FMA(t, dy, dy, t);
                F2FMA(t, dz, dz, t);
                float t0, t1; f2unpack(t, t0, t1);
                dl[2*j]     = fminf(dl[2*j],     t0);
                dl[2*j + 1] = fminf(dl[2*j + 1], t1);
            }
            float m0 = fmaxf(dl[0],  dl[1]),  m1 = fmaxf(dl[2],  dl[3]);
            float m2 = fmaxf(dl[4],  dl[5]),  m3 = fmaxf(dl[6],  dl[7]);
            float m4 = fmaxf(dl[8],  dl[9]),  m5 = fmaxf(dl[10], dl[11]);
            float m6 = fmaxf(dl[12], dl[13]), m7 = fmaxf(dl[14], dl[15]);
            m0 = fmaxf(m0, m1); m2 = fmaxf(m2, m3);
            m4 = fmaxf(m4, m5); m6 = fmaxf(m6, m7);
            m0 = fmaxf(m0, m2); m4 = fmaxf(m4, m6);
            bm = fmaxf(m0, m4);
            int mi = 0x7fffffff;
#pragma unroll
            for (int k = 0; k < 16; k++)
                if (dl[k] == bm) mi = min(mi, oi[k]);
            bi = mi;
        }

        unsigned mb = __float_as_uint(bm);
        unsigned wm = redux_max_u32(mb);
        unsigned ci = (mb == wm) ? (unsigned)bi : 0x7fffffffu;
        unsigned wi = redux_min_u32(ci);
        if (lane == 0) skey[(s & 1) * 16 + wid] = ((ull)wm << 32) | wi;
        __syncthreads();

        ull k = skey[(s & 1) * 16 + (lane & 15)];
        unsigned v  = (unsigned)(k >> 32);
        unsigned ii = (unsigned)k;
        unsigned gm = redux_max_u32(v);
        unsigned c2 = (v == gm) ? ii : 0x7fffffffu;
        unsigned gi = redux_min_u32(c2);

        const float4 c4 = smc4[gi];           // one broadcast LDS.128
        cx = c4.x; cy = c4.y; cz = c4.z;
        if (tid == 0 && s + 1 < M) {
            ox[s + 1] = cx; oy[s + 1] = cy; oz[s + 1] = cz;
        }
    }
}

// ---------------------------------------------------------------------------
// Kernel 2: ball query (proven config, untouched).
// ---------------------------------------------------------------------------
__global__ __launch_bounds__(128) void bq_kernel(
    const float* __restrict__ coords, const float* __restrict__ centers)
{
    const int gw   = (blockIdx.x * blockDim.x + threadIdx.x) >> 5;
    const int lane = threadIdx.x & 31;
    if (gw >= BATCH * M) return;
    const int b = gw >> 11, m = gw & (M - 1);

    const float* X = coords + (size_t)b * 3 * NPTS;
    const float* Y = X + NPTS;
    const float* Z = X + 2 * NPTS;
    const float* C = centers + (size_t)b * 3 * M;
    const float cx = C[m], cy = C[M + m], cz = C[2 * M + m];

    const int base = gw * KNN;
    int cnt = 0, firstn = 0;

    for (int c0 = 0; c0 < NPTS && cnt < KNN; c0 += 128) {
        unsigned msk[4];
#pragma unroll
        for (int u = 0; u < 4; u++) {
            const int n = c0 + u * 32 + lane;
            float dx = X[n] - cx, dy = Y[n] - cy, dz = Z[n] - cz;
            float d2 = fmaf(dz, dz, fmaf(dy, dy, dx * dx));
            msk[u] = __ballot_sync(0xffffffffu, d2 < R2);
        }
#pragma unroll
        for (int u = 0; u < 4; u++) {
            if (cnt < KNN) {
                const unsigned mask = msk[u];
                const int n = c0 + u * 32 + lane;
                if (cnt == 0 && mask) firstn = c0 + u * 32 + __ffs(mask) - 1;
                bool hit = (mask >> lane) & 1u;
                int pos = cnt + __popc(mask & ((1u << lane) - 1u));
                if (hit && pos < KNN) g_idx[base + pos] = n;
                cnt += __popc(mask);
            }
        }
    }
    for (int j = cnt + lane; j < KNN; j += 32) g_idx[base + j] = firstn;
}

// ---------------------------------------------------------------------------
// Kernel 3: MLP consumer (round-14 proven smem version).
//   h1 = relu(prept[b*NPTS+idx] + (-W1c*c)); then layer2 + layer3 + maxpool.
// ---------------------------------------------------------------------------
__global__ __launch_bounds__(256, 2) void mlp2_kernel(
    const float* __restrict__ centers, float* __restrict__ out)
{
    extern __shared__ float sm[];
    const int tid = threadIdx.x;
    for (int i = tid; i < 3136; i += 256)
        ((float4*)sm)[i] = ((const float4*)(g_w + 2240))[i];
    if (tid < 48)                              // w1 rows 0..2 (w1c) -> tail
        ((float4*)(sm + 12544))[tid] = ((const float4*)g_w)[tid];
    __syncthreads();

    float* w2t = sm;                 // [64][64]
    float* w3t = sm + 4096;          // [64][128]
    const ull* bias2 = (const ull*)(sm + 12352);
    const ull* bias3 = (const ull*)(sm + 12416);
    const float* w1c = sm + 12544;   // [3][64]

    const int wid = tid >> 5, lane = tid & 31;
    const int gw = blockIdx.x * 8 + wid;
    const int b = gw >> 11, m = gw & (M - 1);

    const float* C = centers + (size_t)b * 3 * M;
    const float cx = C[m], cy = C[M + m], cz = C[2 * M + m];

    // center term: lane holds channel-pair 'lane' of (-W1c*c)
    ull pcv;
    {
        const ull w0 = ((const ull*)(w1c))[lane];
        const ull w1 = ((const ull*)(w1c + 64))[lane];
        const ull w2 = ((const ull*)(w1c + 128))[lane];
        F2MUL(pcv, w0, f2pack(-cx, -cx));
        F2FMA(pcv, w1, f2pack(-cy, -cy), pcv);
        F2FMA(pcv, w2, f2pack(-cz, -cz), pcv);
    }

    const int idx = g_idx[gw * KNN + lane];
    const ulonglong2* PP =
        (const ulonglong2*)(g_pp + ((size_t)(b * NPTS + idx)) * 32);

    ull acc[32];
#pragma unroll
    for (int i = 0; i < 32; i++) acc[i] = bias2[i];

    for (int blk = 0; blk < 4; blk++) {
        ulonglong2 pp2[4];
#pragma unroll
        for (int t2 = 0; t2 < 4; t2++) pp2[t2] = PP[blk * 4 + t2];
#pragma unroll
        for (int t = 0; t < 8; t++) {
            ull ppv = (t & 1) ? pp2[t >> 1].y : pp2[t >> 1].x;
            ull pv  = __shfl_sync(0xffffffffu, pcv, blk * 8 + t);
            ull hv; F2ADD(hv, ppv, pv);
            float x0, x1; f2unpack(hv, x0, x1);
            x0 = fmaxf(x0, 0.f); x1 = fmaxf(x1, 0.f);
            const ull xx0 = f2pack(x0, x0), xx1 = f2pack(x1, x1);
            const int c = blk * 16 + 2 * t;
            const ulonglong2* pw0 = (const ulonglong2*)(w2t + c * 64);
            const ulonglong2* pw1 = (const ulonglong2*)(w2t + (c + 1) * 64);
#pragma unroll
            for (int i = 0; i < 16; i++) {
                const ulonglong2 w = pw0[i];
                F2FMA(acc[2 * i],     w.x, xx0, acc[2 * i]);
                F2FMA(acc[2 * i + 1], w.y, xx0, acc[2 * i + 1]);
            }
#pragma unroll
            for (int i = 0; i < 16; i++) {
                const ulonglong2 w = pw1[i];
                F2FMA(acc[2 * i],     w.x, xx1, acc[2 * i]);
                F2FMA(acc[2 * i + 1], w.y, xx1, acc[2 * i + 1]);
            }
        }
    }

    float h2[64];
#pragma unroll
    for (int i = 0; i < 32; i++) {
        float a, c2; f2unpack(acc[i], a, c2);
        h2[2 * i] = fmaxf(a, 0.f); h2[2 * i + 1] = fmaxf(c2, 0.f);
    }

    float* O = out + (size_t)b * 128 * M + m;
    for (int q = 0; q < 4; q++) {
        ull a3[16];
#pragma unroll
        for (int i = 0; i < 16; i++) a3[i] = bias3[q * 16 + i];
#pragma unroll
        for (int c = 0; c < 64; c++) {
            const ull xx = f2pack(h2[c], h2[c]);
            const ulonglong2* pw = (const ulonglong2*)(w3t + c * 128 + q * 32);
#pragma unroll
            for (int i = 0; i < 8; i++) {
                const ulonglong2 w = pw[i];
                F2FMA(a3[2 * i],     w.x, xx, a3[2 * i]);
                F2FMA(a3[2 * i + 1], w.y, xx, a3[2 * i + 1]);
            }
        }
#pragma unroll
        for (int i = 0; i < 16; i++) {
            float u, v; f2unpack(a3[i], u, v);
            u = fmaxf(u, 0.f); v = fmaxf(v, 0.f);
#pragma unroll
            for (int off = 16; off; off >>= 1) {
                u = fmaxf(u, __shfl_xor_sync(0xffffffffu, u, off));
                v = fmaxf(v, __shfl_xor_sync(0xffffffffu, v, off));
            }
            if (lane == 0) {
                O[(q * 32 + 2 * i) * M]     = u;
                O[(q * 32 + 2 * i + 1) * M] = v;
            }
        }
    }
}

// ---------------------------------------------------------------------------
extern "C" void kernel_launch(void* const* d_in, const int* in_sizes, int n_in,
                              void* d_out, int out_size)
{
    const float* feats  = (const float*)d_in[0];
    const float* coords = (const float*)d_in[1];
    const float* W1 = (const float*)d_in[2];
    const float* B1 = (const float*)d_in[3];
    const float* W2 = (const float*)d_in[4];
    const float* B2 = (const float*)d_in[5];
    const float* W3 = (const float*)d_in[6];
    const float* B3 = (const float*)d_in[7];

    float* out     = (float*)d_out;
    float* centers = out + (size_t)BATCH * 128 * M;

    sort_kernel<<<BATCH + (WTOT + 1023) / 1024, 1024>>>(
        coords, W1, B1, W2, B2, W3, B3);

    prept_kernel<<<(BATCH * NPTS) / 256, 256, 2304 * 4>>>(coords, feats);

    const int SMEMF = NPTS * 16 + 2 * 16 * 8;
    cudaFuncSetAttribute(fps_kernel, cudaFuncAttributeMaxDynamicSharedMemorySize, SMEMF);
    fps_kernel<<<BATCH, 512, SMEMF>>>(coords, centers);

    bq_kernel<<<(BATCH * M) / 4, 128>>>(coords, centers);

    const int SMEM2 = 12736 * 4;
    cudaFuncSetAttribute(mlp2_kernel, cudaFuncAttributeMaxDynamicSharedMemorySize, SMEM2);
    mlp2_kernel<<<(BATCH * M) / 8, 256, SMEM2>>>(centers, out);
}